// round 14
// baseline (speedup 1.0000x reference)
#include <cuda_runtime.h>
#include <cstdint>
#include <cstddef>

#define BB 2
#define NTOK 1569
#define CC 768
#define HH 12
#define PP 196
#define FF 8
#define SS 1568
#define SCALE 0.125f

// ---------------- scratch (static device globals: no allocation) ----------------
__device__ float g_qkv[(size_t)BB * NTOK * 3 * CC];   // (B*N, 2304)
__device__ float g_traj[(size_t)BB * SS * FF * CC];   // (B,S,F,C)
__device__ float g_xd[(size_t)BB * SS * CC];          // x_diag (B,S,C)
__device__ float g_q2v[(size_t)BB * SS * CC];         // q2 (B,S,C), pre-scaled
__device__ float g_gb[(size_t)BB * SS * HH * CC];     // g (B,S,H,C)  [used as bf16: half]
__device__ float g_pre[(size_t)BB * NTOK * CC];       // concat(cls_out, out)

// =================== tf32 helpers ===================
__device__ __forceinline__ uint32_t f2tf32(float x) {
    uint32_t r;
    asm("cvt.rna.tf32.f32 %0, %1;" : "=r"(r) : "f"(x));
    return r;
}

__device__ __forceinline__ float4 cvt4(float4 v) {
    float4 o;
    o.x = __uint_as_float(f2tf32(v.x));
    o.y = __uint_as_float(f2tf32(v.y));
    o.z = __uint_as_float(f2tf32(v.z));
    o.w = __uint_as_float(f2tf32(v.w));
    return o;
}

__device__ __forceinline__ uint32_t pack_bf16(float lo, float hi) {
    uint32_t r;
    asm("cvt.rn.bf16x2.f32 %0, %1, %2;" : "=r"(r) : "f"(hi), "f"(lo));
    return r;
}

__device__ __forceinline__ void mma_tf32(float* d, const uint32_t* a, const uint32_t* b) {
    asm volatile(
        "mma.sync.aligned.m16n8k8.row.col.f32.tf32.tf32.f32 "
        "{%0,%1,%2,%3}, {%4,%5,%6,%7}, {%8,%9}, {%0,%1,%2,%3};"
        : "+f"(d[0]), "+f"(d[1]), "+f"(d[2]), "+f"(d[3])
        : "r"(a[0]), "r"(a[1]), "r"(a[2]), "r"(a[3]), "r"(b[0]), "r"(b[1]));
}

#define CP_ASYNC16(dst, src, srcsz) \
    asm volatile("cp.async.cg.shared.global [%0], [%1], 16, %2;" \
                 :: "r"(dst), "l"(src), "r"(srcsz))
#define CP_COMMIT() asm volatile("cp.async.commit_group;")
#define CP_WAIT0() asm volatile("cp.async.wait_group 0;")
#define CP_WAIT1() asm volatile("cp.async.wait_group 1;")

// =================== pipelined tf32 SGEMM, 128x128x32 tile ===================
// C = alpha * A(MxK)@B(KxN) (+bias).  N%128==0, K%32==0, M edge guarded.
// tf32 rounding is done IN PLACE on the smem tile after arrival (out of mma loop).
#define ASTR 36
#define BSTR 136
#define A_TILE (128 * ASTR)
#define B_TILE (32 * BSTR)
#define SG_SMEM_FLOATS (2 * A_TILE + 2 * B_TILE)

__global__ void __launch_bounds__(256, 2) sgemm_tf32_kernel(
    const float* __restrict__ A, const float* __restrict__ B, float* __restrict__ C,
    int M, int N, int K, float alpha, const float* __restrict__ bias)
{
    extern __shared__ float sm[];
    float* As = sm;
    float* Bs = sm + 2 * A_TILE;
    const uint32_t sA0 = (uint32_t)__cvta_generic_to_shared(As);
    const uint32_t sB0 = (uint32_t)__cvta_generic_to_shared(Bs);

    const int tid = threadIdx.x;
    const int lane = tid & 31;
    const int warp = tid >> 5;
    const int gid = lane >> 2;
    const int tig = lane & 3;
    const int warp_m = warp >> 1;
    const int warp_n = warp & 1;
    const int row0 = blockIdx.y * 128;
    const int col0 = blockIdx.x * 128;

    const int a_row[4] = { (tid + 0) >> 3, (tid + 256) >> 3, (tid + 512) >> 3, (tid + 768) >> 3 };
    const int a_kq = (tid & 7) << 2;
    const int b_k[4]  = { (tid + 0) >> 5, (tid + 256) >> 5, (tid + 512) >> 5, (tid + 768) >> 5 };
    const int b_nq = (tid & 31) << 2;

    float acc[2][8][4];
#pragma unroll
    for (int mf = 0; mf < 2; mf++)
#pragma unroll
        for (int nf = 0; nf < 8; nf++)
#pragma unroll
            for (int c = 0; c < 4; c++) acc[mf][nf][c] = 0.f;

    const int nkt = K >> 5;

    {
#pragma unroll
        for (int r = 0; r < 4; r++) {
            int grow = row0 + a_row[r];
            const float* src = A + (size_t)grow * K + a_kq;
            uint32_t dst = sA0 + (uint32_t)((a_row[r] * ASTR + a_kq) << 2);
            CP_ASYNC16(dst, src, grow < M ? 16 : 0);
        }
#pragma unroll
        for (int r = 0; r < 4; r++) {
            const float* src = B + (size_t)b_k[r] * N + col0 + b_nq;
            uint32_t dst = sB0 + (uint32_t)((b_k[r] * BSTR + b_nq) << 2);
            CP_ASYNC16(dst, src, 16);
        }
        CP_COMMIT();
    }

    for (int kt = 0; kt < nkt; kt++) {
        const int cur = kt & 1;
        if (kt + 1 < nkt) {
            const int k0 = (kt + 1) << 5;
            const int nxt = cur ^ 1;
            const uint32_t aoff = sA0 + (uint32_t)(nxt * A_TILE << 2);
            const uint32_t boff = sB0 + (uint32_t)(nxt * B_TILE << 2);
#pragma unroll
            for (int r = 0; r < 4; r++) {
                int grow = row0 + a_row[r];
                const float* src = A + (size_t)grow * K + k0 + a_kq;
                uint32_t dst = aoff + (uint32_t)((a_row[r] * ASTR + a_kq) << 2);
                CP_ASYNC16(dst, src, grow < M ? 16 : 0);
            }
#pragma unroll
            for (int r = 0; r < 4; r++) {
                const float* src = B + (size_t)(k0 + b_k[r]) * N + col0 + b_nq;
                uint32_t dst = boff + (uint32_t)((b_k[r] * BSTR + b_nq) << 2);
                CP_ASYNC16(dst, src, 16);
            }
            CP_COMMIT();
            CP_WAIT1();
        } else {
            CP_WAIT0();
        }
        __syncthreads();

        float* Acur = As + cur * A_TILE;
        float* Bcur = Bs + cur * B_TILE;

        // in-place tf32 rounding of exactly what this thread fetched
#pragma unroll
        for (int r = 0; r < 4; r++) {
            float4* p = (float4*)(Acur + a_row[r] * ASTR + a_kq);
            *p = cvt4(*p);
        }
#pragma unroll
        for (int r = 0; r < 4; r++) {
            float4* p = (float4*)(Bcur + b_k[r] * BSTR + b_nq);
            *p = cvt4(*p);
        }
        __syncthreads();

        const uint32_t* Au = (const uint32_t*)Acur;
        const uint32_t* Bu = (const uint32_t*)Bcur;
#pragma unroll
        for (int s = 0; s < 4; s++) {
            uint32_t a[2][4];
#pragma unroll
            for (int mf = 0; mf < 2; mf++) {
                int mb = warp_m * 32 + mf * 16;
                const uint32_t* ap = Au + (mb + gid) * ASTR + s * 8 + tig;
                a[mf][0] = ap[0];
                a[mf][1] = ap[8 * ASTR];
                a[mf][2] = ap[4];
                a[mf][3] = ap[8 * ASTR + 4];
            }
            uint32_t b[8][2];
#pragma unroll
            for (int nf = 0; nf < 8; nf++) {
                int nb = warp_n * 64 + nf * 8 + gid;
                b[nf][0] = Bu[(s * 8 + tig) * BSTR + nb];
                b[nf][1] = Bu[(s * 8 + tig + 4) * BSTR + nb];
            }
#pragma unroll
            for (int mf = 0; mf < 2; mf++)
#pragma unroll
                for (int nf = 0; nf < 8; nf++)
                    mma_tf32(acc[mf][nf], a[mf], b[nf]);
        }
        __syncthreads();
    }

#pragma unroll
    for (int mf = 0; mf < 2; mf++) {
        int rbase = row0 + warp_m * 32 + mf * 16 + gid;
#pragma unroll
        for (int half = 0; half < 2; half++) {
            int r = rbase + half * 8;
            if (r >= M) continue;
#pragma unroll
            for (int nf = 0; nf < 8; nf++) {
                int cidx = col0 + warp_n * 64 + nf * 8 + tig * 2;
                float2 v;
                v.x = acc[mf][nf][half * 2 + 0] * alpha;
                v.y = acc[mf][nf][half * 2 + 1] * alpha;
                if (bias) { v.x += bias[cidx]; v.y += bias[cidx + 1]; }
                *(float2*)(C + (size_t)r * N + cidx) = v;
            }
        }
    }
}

// =================== pipelined tf32 SGEMM, 64x128x32 tile (high-occupancy) ===================
#define A_TILE64 (64 * ASTR)
#define SG64_SMEM_FLOATS (2 * A_TILE64 + 2 * B_TILE)

__global__ void __launch_bounds__(256, 3) sgemm64_tf32_kernel(
    const float* __restrict__ A, const float* __restrict__ B, float* __restrict__ C,
    int M, int N, int K, float alpha, const float* __restrict__ bias)
{
    extern __shared__ float sm[];
    float* As = sm;
    float* Bs = sm + 2 * A_TILE64;
    const uint32_t sA0 = (uint32_t)__cvta_generic_to_shared(As);
    const uint32_t sB0 = (uint32_t)__cvta_generic_to_shared(Bs);

    const int tid = threadIdx.x;
    const int lane = tid & 31;
    const int warp = tid >> 5;
    const int gid = lane >> 2;
    const int tig = lane & 3;
    const int warp_m = warp >> 1;
    const int warp_n = warp & 1;
    const int row0 = blockIdx.y * 64;
    const int col0 = blockIdx.x * 128;

    const int a_row[2] = { (tid + 0) >> 3, (tid + 256) >> 3 };
    const int a_kq = (tid & 7) << 2;
    const int b_k[4]  = { (tid + 0) >> 5, (tid + 256) >> 5, (tid + 512) >> 5, (tid + 768) >> 5 };
    const int b_nq = (tid & 31) << 2;

    float acc[8][4];
#pragma unroll
    for (int nf = 0; nf < 8; nf++)
#pragma unroll
        for (int c = 0; c < 4; c++) acc[nf][c] = 0.f;

    const int nkt = K >> 5;

    {
#pragma unroll
        for (int r = 0; r < 2; r++) {
            int grow = row0 + a_row[r];
            const float* src = A + (size_t)grow * K + a_kq;
            uint32_t dst = sA0 + (uint32_t)((a_row[r] * ASTR + a_kq) << 2);
            CP_ASYNC16(dst, src, grow < M ? 16 : 0);
        }
#pragma unroll
        for (int r = 0; r < 4; r++) {
            const float* src = B + (size_t)b_k[r] * N + col0 + b_nq;
            uint32_t dst = sB0 + (uint32_t)((b_k[r] * BSTR + b_nq) << 2);
            CP_ASYNC16(dst, src, 16);
        }
        CP_COMMIT();
    }

    for (int kt = 0; kt < nkt; kt++) {
        const int cur = kt & 1;
        if (kt + 1 < nkt) {
            const int k0 = (kt + 1) << 5;
            const int nxt = cur ^ 1;
            const uint32_t aoff = sA0 + (uint32_t)(nxt * A_TILE64 << 2);
            const uint32_t boff = sB0 + (uint32_t)(nxt * B_TILE << 2);
#pragma unroll
            for (int r = 0; r < 2; r++) {
                int grow = row0 + a_row[r];
                const float* src = A + (size_t)grow * K + k0 + a_kq;
                uint32_t dst = aoff + (uint32_t)((a_row[r] * ASTR + a_kq) << 2);
                CP_ASYNC16(dst, src, grow < M ? 16 : 0);
            }
#pragma unroll
            for (int r = 0; r < 4; r++) {
                const float* src = B + (size_t)(k0 + b_k[r]) * N + col0 + b_nq;
                uint32_t dst = boff + (uint32_t)((b_k[r] * BSTR + b_nq) << 2);
                CP_ASYNC16(dst, src, 16);
            }
            CP_COMMIT();
            CP_WAIT1();
        } else {
            CP_WAIT0();
        }
        __syncthreads();

        float* Acur = As + cur * A_TILE64;
        float* Bcur = Bs + cur * B_TILE;

#pragma unroll
        for (int r = 0; r < 2; r++) {
            float4* p = (float4*)(Acur + a_row[r] * ASTR + a_kq);
            *p = cvt4(*p);
        }
#pragma unroll
        for (int r = 0; r < 4; r++) {
            float4* p = (float4*)(Bcur + b_k[r] * BSTR + b_nq);
            *p = cvt4(*p);
        }
        __syncthreads();

        const uint32_t* Au = (const uint32_t*)Acur;
        const uint32_t* Bu = (const uint32_t*)Bcur;
#pragma unroll
        for (int s = 0; s < 4; s++) {
            uint32_t a[4];
            {
                const uint32_t* ap = Au + (warp_m * 16 + gid) * ASTR + s * 8 + tig;
                a[0] = ap[0];
                a[1] = ap[8 * ASTR];
                a[2] = ap[4];
                a[3] = ap[8 * ASTR + 4];
            }
            uint32_t b[8][2];
#pragma unroll
            for (int nf = 0; nf < 8; nf++) {
                int nb = warp_n * 64 + nf * 8 + gid;
                b[nf][0] = Bu[(s * 8 + tig) * BSTR + nb];
                b[nf][1] = Bu[(s * 8 + tig + 4) * BSTR + nb];
            }
#pragma unroll
            for (int nf = 0; nf < 8; nf++)
                mma_tf32(acc[nf], a, b[nf]);
        }
        __syncthreads();
    }

    {
        int rbase = row0 + warp_m * 16 + gid;
#pragma unroll
        for (int half = 0; half < 2; half++) {
            int r = rbase + half * 8;
            if (r >= M) continue;
#pragma unroll
            for (int nf = 0; nf < 8; nf++) {
                int cidx = col0 + warp_n * 64 + nf * 8 + tig * 2;
                float2 v;
                v.x = acc[nf][half * 2 + 0] * alpha;
                v.y = acc[nf][half * 2 + 1] * alpha;
                if (bias) { v.x += bias[cidx]; v.y += bias[cidx + 1]; }
                *(float2*)(C + (size_t)r * N + cidx) = v;
            }
        }
    }
}

// =================== tf32 TC g-GEMM (batched per head), bf16 output ===================
// g[m, h, c] = sum_d q2[m, h*64+d] * Wpkv[c, h*64+d], stored bf16-packed (2 per u32).
#define GSTR 68
#define G_SMEM_FLOATS (64 * GSTR + 128 * GSTR)

__global__ void __launch_bounds__(256, 3) g_tc_kernel(
    const float* __restrict__ q2, const float* __restrict__ Wpkv, uint32_t* __restrict__ g32)
{
    extern __shared__ float sm[];
    float* Asm = sm;
    float* Bsm = sm + 64 * GSTR;

    const int t = threadIdx.x;
    const int lane = t & 31;
    const int warp = t >> 5;
    const int gid = lane >> 2;
    const int tig = lane & 3;
    const int warp_m = warp >> 1;
    const int warp_n = warp & 1;
    const int m0 = blockIdx.x * 64;
    const int n0 = blockIdx.y * 128;
    const int h = blockIdx.z;

#pragma unroll
    for (int r = 0; r < 4; r++) {
        int idx = t + (r << 8);
        int mm = idx >> 4, dv = (idx & 15) << 2;
        float4 v = *(const float4*)(q2 + (size_t)(m0 + mm) * CC + h * 64 + dv);
        *(float4*)(Asm + mm * GSTR + dv) = cvt4(v);
    }
#pragma unroll
    for (int r = 0; r < 8; r++) {
        int idx = t + (r << 8);
        int cc = idx >> 4, dv = (idx & 15) << 2;
        float4 v = *(const float4*)(Wpkv + (size_t)(n0 + cc) * (2 * CC) + h * 64 + dv);
        *(float4*)(Bsm + cc * GSTR + dv) = cvt4(v);
    }
    __syncthreads();

    float acc[8][4];
#pragma unroll
    for (int nf = 0; nf < 8; nf++)
#pragma unroll
        for (int c = 0; c < 4; c++) acc[nf][c] = 0.f;

    const uint32_t* Au = (const uint32_t*)Asm;
    const uint32_t* Bu = (const uint32_t*)Bsm;
#pragma unroll
    for (int s = 0; s < 8; s++) {
        uint32_t a[4];
        const uint32_t* ap = Au + (warp_m * 16 + gid) * GSTR + s * 8 + tig;
        a[0] = ap[0];
        a[1] = ap[8 * GSTR];
        a[2] = ap[4];
        a[3] = ap[8 * GSTR + 4];
#pragma unroll
        for (int nf = 0; nf < 8; nf++) {
            int nb = warp_n * 64 + nf * 8 + gid;
            uint32_t b[2];
            b[0] = Bu[nb * GSTR + s * 8 + tig];
            b[1] = Bu[nb * GSTR + s * 8 + tig + 4];
            mma_tf32(acc[nf], a, b);
        }
    }

#pragma unroll
    for (int half = 0; half < 2; half++) {
        int m = m0 + warp_m * 16 + gid + half * 8;
        uint32_t* grow = g32 + ((size_t)m * HH + h) * (CC / 2) + n0 / 2;
#pragma unroll
        for (int nf = 0; nf < 8; nf++) {
            int col = warp_n * 64 + nf * 8 + tig * 2;
            grow[col >> 1] = pack_bf16(acc[nf][half * 2 + 0], acc[nf][half * 2 + 1]);
        }
    }
}

// ---------------- CLS attention: one block per (b,h) ----------------
__global__ void __launch_bounds__(256) cls_kernel(const float* __restrict__ qkv,
                                                  float* __restrict__ pre)
{
    __shared__ float qv[64];
    __shared__ float logit[NTOK];
    __shared__ float red[256];
    const int bh = blockIdx.x;
    const int b = bh / HH, h = bh % HH;
    const int t = threadIdx.x;
    const int lane = t & 31, warp = t >> 5;
    const float* base = qkv + (size_t)b * NTOK * (3 * CC);

    if (t < 64) qv[t] = base[h * 64 + t] * SCALE;
    __syncthreads();

    // QK: warp per token (coalesced 64-float read split as float2/lane)
    for (int n = warp; n < NTOK; n += 8) {
        const float* kr = base + (size_t)n * (3 * CC) + CC + h * 64;
        float2 kv2 = *(const float2*)(kr + lane * 2);
        float s = kv2.x * qv[lane * 2] + kv2.y * qv[lane * 2 + 1];
#pragma unroll
        for (int o = 16; o; o >>= 1) s += __shfl_xor_sync(0xffffffffu, s, o);
        if (lane == 0) logit[n] = s;
    }
    __syncthreads();

    float m = -1e30f;
    for (int n = t; n < NTOK; n += 256) m = fmaxf(m, logit[n]);
    red[t] = m; __syncthreads();
    for (int s2 = 128; s2 > 0; s2 >>= 1) {
        if (t < s2) red[t] = fmaxf(red[t], red[t + s2]);
        __syncthreads();
    }
    const float mx = red[0];
    __syncthreads();

    float ssum = 0.f;
    for (int n = t; n < NTOK; n += 256) {
        float e = __expf(logit[n] - mx);
        logit[n] = e;
        ssum += e;
    }
    red[t] = ssum; __syncthreads();
    for (int s2 = 128; s2 > 0; s2 >>= 1) {
        if (t < s2) red[t] += red[t + s2];
        __syncthreads();
    }
    const float inv = 1.f / red[0];
    __syncthreads();

    const int dd = t & 63, grp = t >> 6;
    float acc = 0.f;
    for (int n = grp; n < NTOK; n += 4)
        acc += logit[n] * base[(size_t)n * (3 * CC) + 2 * CC + h * 64 + dd];
    red[t] = acc; __syncthreads();
    if (t < 64) {
        float v = red[t] + red[t + 64] + red[t + 128] + red[t + 192];
        pre[(size_t)b * NTOK * CC + h * 64 + t] = v * inv;
    }
}

// ---------------- tf32 tensor-core spatial attention (+ fused x_diag) ----------------
#define QT 32
#define NPAD 208
#define QSTR 68
#define KSTR 216
#define LSTR 212
#define VSTR 72
#define SPA2_POOL 14976
#define SPA2_SMEM_FLOATS (QT*QSTR + QT*LSTR + SPA2_POOL)

__global__ void __launch_bounds__(128, 2) spatial_tc_kernel(const float* __restrict__ qkv,
                                                            float* __restrict__ traj,
                                                            float* __restrict__ xd)
{
    extern __shared__ float sm[];
    uint32_t* qs = (uint32_t*)sm;
    float* ls = sm + QT * QSTR;
    uint32_t* ks = (uint32_t*)(ls + QT * LSTR);
    uint32_t* vs = ks;

    const int t = threadIdx.x;
    const int lane = t & 31, warp = t >> 5;
    const int gid = lane >> 2, tig = lane & 3;
    const int warp_m = warp >> 1;
    const int warp_n = warp & 1;
    const int bh = blockIdx.y;
    const int b = bh / HH, h = bh % HH;
    const int q0 = blockIdx.x * QT;
    const float* base = qkv + (size_t)b * NTOK * (3 * CC);

#pragma unroll
    for (int r = 0; r < 4; r++) {
        int idx = t + r * 128;
        int q = idx >> 4, dv = (idx & 15) << 2;
        float4 v = *(const float4*)(base + (size_t)(1 + q0 + q) * (3 * CC) + h * 64 + dv);
        uint32_t* dst = qs + q * QSTR + dv;
        dst[0] = f2tf32(v.x * SCALE); dst[1] = f2tf32(v.y * SCALE);
        dst[2] = f2tf32(v.z * SCALE); dst[3] = f2tf32(v.w * SCALE);
    }

    for (int f = 0; f < FF; f++) {
        for (int idx = t; idx < PP * 16; idx += 128) {
            int n = idx >> 4, dv = (idx & 15) << 2;
            float4 v = *(const float4*)(base + (size_t)(1 + f * PP + n) * (3 * CC) + CC + h * 64 + dv);
            ks[(dv + 0) * KSTR + n] = f2tf32(v.x);
            ks[(dv + 1) * KSTR + n] = f2tf32(v.y);
            ks[(dv + 2) * KSTR + n] = f2tf32(v.z);
            ks[(dv + 3) * KSTR + n] = f2tf32(v.w);
        }
        for (int i = t; i < 64 * 12; i += 128) {
            int d = i / 12, n = 196 + (i % 12);
            ks[d * KSTR + n] = 0u;
        }
        __syncthreads();

        {
            float acc[13][4];
#pragma unroll
            for (int nf = 0; nf < 13; nf++)
#pragma unroll
                for (int c = 0; c < 4; c++) acc[nf][c] = 0.f;
#pragma unroll
            for (int s = 0; s < 8; s++) {
                uint32_t a[4];
                const uint32_t* ap = qs + (warp_m * 16 + gid) * QSTR + s * 8 + tig;
                a[0] = ap[0];
                a[1] = ap[8 * QSTR];
                a[2] = ap[4];
                a[3] = ap[8 * QSTR + 4];
#pragma unroll
                for (int nf = 0; nf < 13; nf++) {
                    int nb = warp_n * 104 + nf * 8 + gid;
                    uint32_t bfr[2];
                    bfr[0] = ks[(s * 8 + tig) * KSTR + nb];
                    bfr[1] = ks[(s * 8 + tig + 4) * KSTR + nb];
                    mma_tf32(acc[nf], a, bfr);
                }
            }
#pragma unroll
            for (int nf = 0; nf < 13; nf++) {
                int col = warp_n * 104 + nf * 8 + tig * 2;
                int row = warp_m * 16 + gid;
                *(float2*)(ls + row * LSTR + col) = make_float2(acc[nf][0], acc[nf][1]);
                *(float2*)(ls + (row + 8) * LSTR + col) = make_float2(acc[nf][2], acc[nf][3]);
            }
        }
        __syncthreads();

        for (int idx = t; idx < PP * 16; idx += 128) {
            int n = idx >> 4, dv = (idx & 15) << 2;
            float4 v = *(const float4*)(base + (size_t)(1 + f * PP + n) * (3 * CC) + 2 * CC + h * 64 + dv);
            uint32_t* dst = vs + n * VSTR + dv;
            dst[0] = f2tf32(v.x); dst[1] = f2tf32(v.y);
            dst[2] = f2tf32(v.z); dst[3] = f2tf32(v.w);
        }

        for (int i = 0; i < 8; i++) {
            int qq = warp * 8 + i;
            float* row = ls + qq * LSTR;
            float m = -1e30f;
            for (int n = lane; n < PP; n += 32) m = fmaxf(m, row[n]);
#pragma unroll
            for (int o = 16; o; o >>= 1) m = fmaxf(m, __shfl_xor_sync(0xffffffffu, m, o));
            float ssum = 0.f;
            float ev[7];
            int cnt = 0;
            for (int n = lane; n < PP; n += 32) {
                float e = __expf(row[n] - m);
                ev[cnt++] = e;
                ssum += e;
            }
#pragma unroll
            for (int o = 16; o; o >>= 1) ssum += __shfl_xor_sync(0xffffffffu, ssum, o);
            float inv = 1.f / ssum;
            cnt = 0;
            for (int n = lane; n < PP; n += 32)
                ((uint32_t*)row)[n] = f2tf32(ev[cnt++] * inv);
            if (lane < 12) ((uint32_t*)row)[196 + lane] = 0u;
        }
        __syncthreads();

        {
            float acc[4][4];
#pragma unroll
            for (int nf = 0; nf < 4; nf++)
#pragma unroll
                for (int c = 0; c < 4; c++) acc[nf][c] = 0.f;
            const uint32_t* lsu = (const uint32_t*)ls;
#pragma unroll
            for (int s = 0; s < 26; s++) {
                uint32_t a[4];
                const uint32_t* ap = lsu + (warp_m * 16 + gid) * LSTR + s * 8 + tig;
                a[0] = ap[0];
                a[1] = ap[8 * LSTR];
                a[2] = ap[4];
                a[3] = ap[8 * LSTR + 4];
#pragma unroll
                for (int nf = 0; nf < 4; nf++) {
                    int nb = warp_n * 32 + nf * 8 + gid;
                    uint32_t bfr[2];
                    bfr[0] = vs[(s * 8 + tig) * VSTR + nb];
                    bfr[1] = vs[(s * 8 + tig + 4) * VSTR + nb];
                    mma_tf32(acc[nf], a, bfr);
                }
            }
#pragma unroll
            for (int half = 0; half < 2; half++) {
                int q = q0 + warp_m * 16 + gid + half * 8;
                float* orow = traj + (((size_t)(b * SS + q) * FF + f) * CC + h * 64);
                const bool diag = (f == q / PP);
                float* xrow = xd + ((size_t)(b * SS + q) * CC + h * 64);
#pragma unroll
                for (int nf = 0; nf < 4; nf++) {
                    int col = warp_n * 32 + nf * 8 + tig * 2;
                    float2 v = make_float2(acc[nf][half * 2 + 0], acc[nf][half * 2 + 1]);
                    *(float2*)(orow + col) = v;
                    if (diag) *(float2*)(xrow + col) = v;
                }
            }
        }
        __syncthreads();
    }
}

// ---------------- phase-2: logits + softmax + output + attn write ----------------
// g arrives bf16-packed (2 per uint32); unpacked to fp32 smem at fill (exact widening).
#define P2_SMEM_FLOATS (FF * CC + HH * CC + 96 + 96)
__global__ void __launch_bounds__(256) phase2_kernel(
    const float* __restrict__ traj, const uint32_t* __restrict__ g32,
    float* __restrict__ pre, float* __restrict__ attn_out, int write_attn)
{
    extern __shared__ float sm[];
    float* trs = sm;
    float* gs = sm + FF * CC;
    float* lsm = gs + HH * CC;
    float* am = lsm + 96;

    const int bs = blockIdx.x;
    const int b = bs / SS, s = bs % SS;
    const int t = threadIdx.x;

    const float* tr = traj + (size_t)bs * FF * CC;
    for (int i = t; i < FF * CC / 4; i += 256)
        ((float4*)trs)[i] = ((const float4*)tr)[i];
    const uint32_t* gg = g32 + (size_t)bs * HH * (CC / 2);
    for (int i = t; i < HH * CC / 2; i += 256) {
        uint32_t w = gg[i];
        float2 v;
        v.x = __uint_as_float(w << 16);
        v.y = __uint_as_float(w & 0xffff0000u);
        *(float2*)(gs + 2 * i) = v;
    }
    __syncthreads();

    {
        const int lane = t & 31, w = t >> 5;
        for (int p = w * 12; p < w * 12 + 12; p++) {
            int h = p >> 3, f = p & 7;
            float ssum = 0.f;
            for (int c = lane; c < CC; c += 32)
                ssum += trs[f * CC + c] * gs[h * CC + c];
#pragma unroll
            for (int o = 16; o; o >>= 1) ssum += __shfl_xor_sync(0xffffffffu, ssum, o);
            if (lane == 0) lsm[p] = ssum;
        }
    }
    __syncthreads();

    if (t < HH) {
        int h = t;
        float m = -1e30f;
#pragma unroll
        for (int f = 0; f < FF; f++) m = fmaxf(m, lsm[h * 8 + f]);
        float e[FF];
        float ssum = 0.f;
#pragma unroll
        for (int f = 0; f < FF; f++) { e[f] = __expf(lsm[h * 8 + f] - m); ssum += e[f]; }
        float inv = 1.f / ssum;
#pragma unroll
        for (int f = 0; f < FF; f++) am[h * 8 + f] = e[f] * inv;
    }
    __syncthreads();

    if (write_attn && t < 96) {
        int h = t >> 3, f = t & 7;
        attn_out[(((size_t)b * HH + h) * SS + s) * FF + f] = am[t];
    }

    for (int c = t; c < CC; c += 256) {
        int h = c >> 6;
        float acc = 0.f;
#pragma unroll
        for (int f = 0; f < FF; f++) acc += am[h * 8 + f] * trs[f * CC + c];
        pre[((size_t)b * NTOK + 1 + s) * CC + c] = acc;
    }
}

// ---------------- host ----------------
extern "C" void kernel_launch(void* const* d_in, const int* in_sizes, int n_in,
                              void* d_out, int out_size)
{
    const float* x     = (const float*)d_in[0];
    const float* Wqkv  = (const float*)d_in[1];
    const float* Wpq   = (const float*)d_in[2];
    const float* Wpkv  = (const float*)d_in[3];
    const float* Wproj = (const float*)d_in[4];
    const float* bproj = (const float*)d_in[5];

    float *qkv, *traj, *xd, *q2, *gb, *pre;
    cudaGetSymbolAddress((void**)&qkv,  g_qkv);
    cudaGetSymbolAddress((void**)&traj, g_traj);
    cudaGetSymbolAddress((void**)&xd,   g_xd);
    cudaGetSymbolAddress((void**)&q2,   g_q2v);
    cudaGetSymbolAddress((void**)&gb,   g_gb);
    cudaGetSymbolAddress((void**)&pre,  g_pre);
    uint32_t* g32 = (uint32_t*)gb;   // bf16-packed g

    const size_t OUT_MAIN = (size_t)BB * NTOK * CC;
    const size_t OUT_ATTN = (size_t)BB * HH * SS * FF;
    int write_attn = ((size_t)out_size >= OUT_MAIN + OUT_ATTN) ? 1 : 0;
    float* attn_ptr = (float*)d_out + OUT_MAIN;

    const int sg_smem   = SG_SMEM_FLOATS * 4;
    const int sg64_smem = SG64_SMEM_FLOATS * 4;
    const int g_smem    = G_SMEM_FLOATS * 4;
    const int spa_smem  = SPA2_SMEM_FLOATS * 4;
    const int p2_smem   = P2_SMEM_FLOATS * 4;
    cudaFuncSetAttribute(sgemm_tf32_kernel,   cudaFuncAttributeMaxDynamicSharedMemorySize, sg_smem);
    cudaFuncSetAttribute(sgemm64_tf32_kernel, cudaFuncAttributeMaxDynamicSharedMemorySize, sg64_smem);
    cudaFuncSetAttribute(g_tc_kernel,         cudaFuncAttributeMaxDynamicSharedMemorySize, g_smem);
    cudaFuncSetAttribute(spatial_tc_kernel,   cudaFuncAttributeMaxDynamicSharedMemorySize, spa_smem);
    cudaFuncSetAttribute(phase2_kernel,       cudaFuncAttributeMaxDynamicSharedMemorySize, p2_smem);

    // 1) qkv = x @ W_qkv  [tf32 TC, 128-tile]
    sgemm_tf32_kernel<<<dim3((3 * CC) / 128, (BB * NTOK + 127) / 128), 256, sg_smem>>>(
        x, Wqkv, qkv, BB * NTOK, 3 * CC, CC, 1.0f, nullptr);

    // 2) CLS attention -> pre[b, 0, :]
    cls_kernel<<<BB * HH, 256>>>(qkv, pre);

    // 3) spatial attention (tf32 TC) -> traj, fused x_diag -> xd
    spatial_tc_kernel<<<dim3(SS / QT, BB * HH), 128, spa_smem>>>(qkv, traj, xd);

    // 4) q2 = scale * x_diag @ W_pq  [tf32 TC, 64-tile]
    sgemm64_tf32_kernel<<<dim3(CC / 128, (BB * SS + 63) / 64), 256, sg64_smem>>>(
        xd, Wpq, q2, BB * SS, CC, CC, SCALE, nullptr);

    // 5) g = per-head W_pk @ q2  [tf32 TC, bf16 output]
    g_tc_kernel<<<dim3((BB * SS) / 64, CC / 128, HH), 256, g_smem>>>(q2, Wpkv, g32);

    // 6) phase-2 attention (bf16 g input)
    phase2_kernel<<<BB * SS, 256, p2_smem>>>(traj, g32, pre, attn_ptr, write_attn);

    // 7) out = pre @ W_proj + b_proj  [tf32 TC, 64-tile]
    sgemm64_tf32_kernel<<<dim3(CC / 128, (BB * NTOK + 63) / 64), 256, sg64_smem>>>(
        pre, Wproj, (float*)d_out, BB * NTOK, CC, CC, 1.0f, bproj);
}

// round 16
// speedup vs baseline: 1.0378x; 1.0378x over previous
#include <cuda_runtime.h>
#include <cstdint>
#include <cstddef>

#define BB 2
#define NTOK 1569
#define CC 768
#define HH 12
#define PP 196
#define FF 8
#define SS 1568
#define SCALE 0.125f

// ---------------- scratch (static device globals: no allocation) ----------------
__device__ float g_qkv[(size_t)BB * NTOK * 3 * CC];   // (B*N, 2304)
__device__ float g_traj[(size_t)BB * SS * FF * CC];   // (B,S,F,C)
__device__ float g_xd[(size_t)BB * SS * CC];          // x_diag (B,S,C), tf32-rounded
__device__ float g_q2v[(size_t)BB * SS * CC];         // q2 (B,S,C), pre-scaled
__device__ float g_gb[(size_t)BB * SS * HH * CC];     // g (bf16-packed)
__device__ float g_pre[(size_t)BB * NTOK * CC];       // concat(cls_out, out), tf32-rounded
__device__ float g_xr[(size_t)BB * NTOK * CC];        // x, tf32-rounded
__device__ float g_wr[(size_t)CC * 3 * CC + (size_t)CC * CC + (size_t)CC * CC]; // Wqkv|Wpq|Wproj rounded

// =================== tf32 helpers ===================
__device__ __forceinline__ uint32_t f2tf32(float x) {
    uint32_t r;
    asm("cvt.rna.tf32.f32 %0, %1;" : "=r"(r) : "f"(x));
    return r;
}

__device__ __forceinline__ float4 cvt4(float4 v) {
    float4 o;
    o.x = __uint_as_float(f2tf32(v.x));
    o.y = __uint_as_float(f2tf32(v.y));
    o.z = __uint_as_float(f2tf32(v.z));
    o.w = __uint_as_float(f2tf32(v.w));
    return o;
}

__device__ __forceinline__ uint32_t pack_bf16(float lo, float hi) {
    uint32_t r;
    asm("cvt.rn.bf16x2.f32 %0, %1, %2;" : "=r"(r) : "f"(hi), "f"(lo));
    return r;
}

__device__ __forceinline__ void mma_tf32(float* d, const uint32_t* a, const uint32_t* b) {
    asm volatile(
        "mma.sync.aligned.m16n8k8.row.col.f32.tf32.tf32.f32 "
        "{%0,%1,%2,%3}, {%4,%5,%6,%7}, {%8,%9}, {%0,%1,%2,%3};"
        : "+f"(d[0]), "+f"(d[1]), "+f"(d[2]), "+f"(d[3])
        : "r"(a[0]), "r"(a[1]), "r"(a[2]), "r"(a[3]), "r"(b[0]), "r"(b[1]));
}

#define CP_ASYNC16(dst, src, srcsz) \
    asm volatile("cp.async.cg.shared.global [%0], [%1], 16, %2;" \
                 :: "r"(dst), "l"(src), "r"(srcsz))
#define CP_COMMIT() asm volatile("cp.async.commit_group;")
#define CP_WAIT0() asm volatile("cp.async.wait_group 0;")
#define CP_WAIT1() asm volatile("cp.async.wait_group 1;")

// =================== elementwise tf32 pre-round ===================
__global__ void round_tf32_kernel(const float* __restrict__ in, float* __restrict__ out, int n4)
{
    int i = blockIdx.x * blockDim.x + threadIdx.x;
    if (i < n4) ((float4*)out)[i] = cvt4(((const float4*)in)[i]);
}

// =================== pipelined tf32 SGEMM, 128x128x32 tile ===================
// Inputs must already be tf32-rounded. No CVT in the hot loop.
#define ASTR 36
#define BSTR 136
#define A_TILE (128 * ASTR)
#define B_TILE (32 * BSTR)
#define SG_SMEM_FLOATS (2 * A_TILE + 2 * B_TILE)

__global__ void __launch_bounds__(256, 2) sgemm_tf32_kernel(
    const float* __restrict__ A, const float* __restrict__ B, float* __restrict__ C,
    int M, int N, int K, float alpha, const float* __restrict__ bias, int round_out)
{
    extern __shared__ float sm[];
    float* As = sm;
    float* Bs = sm + 2 * A_TILE;
    const uint32_t sA0 = (uint32_t)__cvta_generic_to_shared(As);
    const uint32_t sB0 = (uint32_t)__cvta_generic_to_shared(Bs);

    const int tid = threadIdx.x;
    const int lane = tid & 31;
    const int warp = tid >> 5;
    const int gid = lane >> 2;
    const int tig = lane & 3;
    const int warp_m = warp >> 1;
    const int warp_n = warp & 1;
    const int row0 = blockIdx.y * 128;
    const int col0 = blockIdx.x * 128;

    const int a_row[4] = { (tid + 0) >> 3, (tid + 256) >> 3, (tid + 512) >> 3, (tid + 768) >> 3 };
    const int a_kq = (tid & 7) << 2;
    const int b_k[4]  = { (tid + 0) >> 5, (tid + 256) >> 5, (tid + 512) >> 5, (tid + 768) >> 5 };
    const int b_nq = (tid & 31) << 2;

    float acc[2][8][4];
#pragma unroll
    for (int mf = 0; mf < 2; mf++)
#pragma unroll
        for (int nf = 0; nf < 8; nf++)
#pragma unroll
            for (int c = 0; c < 4; c++) acc[mf][nf][c] = 0.f;

    const int nkt = K >> 5;

    {
#pragma unroll
        for (int r = 0; r < 4; r++) {
            int grow = row0 + a_row[r];
            const float* src = A + (size_t)grow * K + a_kq;
            uint32_t dst = sA0 + (uint32_t)((a_row[r] * ASTR + a_kq) << 2);
            CP_ASYNC16(dst, src, grow < M ? 16 : 0);
        }
#pragma unroll
        for (int r = 0; r < 4; r++) {
            const float* src = B + (size_t)b_k[r] * N + col0 + b_nq;
            uint32_t dst = sB0 + (uint32_t)((b_k[r] * BSTR + b_nq) << 2);
            CP_ASYNC16(dst, src, 16);
        }
        CP_COMMIT();
    }

    for (int kt = 0; kt < nkt; kt++) {
        const int cur = kt & 1;
        if (kt + 1 < nkt) {
            const int k0 = (kt + 1) << 5;
            const int nxt = cur ^ 1;
            const uint32_t aoff = sA0 + (uint32_t)(nxt * A_TILE << 2);
            const uint32_t boff = sB0 + (uint32_t)(nxt * B_TILE << 2);
#pragma unroll
            for (int r = 0; r < 4; r++) {
                int grow = row0 + a_row[r];
                const float* src = A + (size_t)grow * K + k0 + a_kq;
                uint32_t dst = aoff + (uint32_t)((a_row[r] * ASTR + a_kq) << 2);
                CP_ASYNC16(dst, src, grow < M ? 16 : 0);
            }
#pragma unroll
            for (int r = 0; r < 4; r++) {
                const float* src = B + (size_t)(k0 + b_k[r]) * N + col0 + b_nq;
                uint32_t dst = boff + (uint32_t)((b_k[r] * BSTR + b_nq) << 2);
                CP_ASYNC16(dst, src, 16);
            }
            CP_COMMIT();
            CP_WAIT1();
        } else {
            CP_WAIT0();
        }
        __syncthreads();

        const uint32_t* Au = (const uint32_t*)(As + cur * A_TILE);
        const uint32_t* Bu = (const uint32_t*)(Bs + cur * B_TILE);
#pragma unroll
        for (int s = 0; s < 4; s++) {
            uint32_t a[2][4];
#pragma unroll
            for (int mf = 0; mf < 2; mf++) {
                int mb = warp_m * 32 + mf * 16;
                const uint32_t* ap = Au + (mb + gid) * ASTR + s * 8 + tig;
                a[mf][0] = ap[0];
                a[mf][1] = ap[8 * ASTR];
                a[mf][2] = ap[4];
                a[mf][3] = ap[8 * ASTR + 4];
            }
            uint32_t b[8][2];
#pragma unroll
            for (int nf = 0; nf < 8; nf++) {
                int nb = warp_n * 64 + nf * 8 + gid;
                b[nf][0] = Bu[(s * 8 + tig) * BSTR + nb];
                b[nf][1] = Bu[(s * 8 + tig + 4) * BSTR + nb];
            }
#pragma unroll
            for (int mf = 0; mf < 2; mf++)
#pragma unroll
                for (int nf = 0; nf < 8; nf++)
                    mma_tf32(acc[mf][nf], a[mf], b[nf]);
        }
        __syncthreads();
    }

#pragma unroll
    for (int mf = 0; mf < 2; mf++) {
        int rbase = row0 + warp_m * 32 + mf * 16 + gid;
#pragma unroll
        for (int half = 0; half < 2; half++) {
            int r = rbase + half * 8;
            if (r >= M) continue;
#pragma unroll
            for (int nf = 0; nf < 8; nf++) {
                int cidx = col0 + warp_n * 64 + nf * 8 + tig * 2;
                float2 v;
                v.x = acc[mf][nf][half * 2 + 0] * alpha;
                v.y = acc[mf][nf][half * 2 + 1] * alpha;
                if (bias) { v.x += bias[cidx]; v.y += bias[cidx + 1]; }
                if (round_out) {
                    v.x = __uint_as_float(f2tf32(v.x));
                    v.y = __uint_as_float(f2tf32(v.y));
                }
                *(float2*)(C + (size_t)r * N + cidx) = v;
            }
        }
    }
}

// =================== pipelined tf32 SGEMM, 64x128x32 tile (high-occupancy) ===================
#define A_TILE64 (64 * ASTR)
#define SG64_SMEM_FLOATS (2 * A_TILE64 + 2 * B_TILE)

__global__ void __launch_bounds__(256, 3) sgemm64_tf32_kernel(
    const float* __restrict__ A, const float* __restrict__ B, float* __restrict__ C,
    int M, int N, int K, float alpha, const float* __restrict__ bias)
{
    extern __shared__ float sm[];
    float* As = sm;
    float* Bs = sm + 2 * A_TILE64;
    const uint32_t sA0 = (uint32_t)__cvta_generic_to_shared(As);
    const uint32_t sB0 = (uint32_t)__cvta_generic_to_shared(Bs);

    const int tid = threadIdx.x;
    const int lane = tid & 31;
    const int warp = tid >> 5;
    const int gid = lane >> 2;
    const int tig = lane & 3;
    const int warp_m = warp >> 1;
    const int warp_n = warp & 1;
    const int row0 = blockIdx.y * 64;
    const int col0 = blockIdx.x * 128;

    const int a_row[2] = { (tid + 0) >> 3, (tid + 256) >> 3 };
    const int a_kq = (tid & 7) << 2;
    const int b_k[4]  = { (tid + 0) >> 5, (tid + 256) >> 5, (tid + 512) >> 5, (tid + 768) >> 5 };
    const int b_nq = (tid & 31) << 2;

    float acc[8][4];
#pragma unroll
    for (int nf = 0; nf < 8; nf++)
#pragma unroll
        for (int c = 0; c < 4; c++) acc[nf][c] = 0.f;

    const int nkt = K >> 5;

    {
#pragma unroll
        for (int r = 0; r < 2; r++) {
            int grow = row0 + a_row[r];
            const float* src = A + (size_t)grow * K + a_kq;
            uint32_t dst = sA0 + (uint32_t)((a_row[r] * ASTR + a_kq) << 2);
            CP_ASYNC16(dst, src, grow < M ? 16 : 0);
        }
#pragma unroll
        for (int r = 0; r < 4; r++) {
            const float* src = B + (size_t)b_k[r] * N + col0 + b_nq;
            uint32_t dst = sB0 + (uint32_t)((b_k[r] * BSTR + b_nq) << 2);
            CP_ASYNC16(dst, src, 16);
        }
        CP_COMMIT();
    }

    for (int kt = 0; kt < nkt; kt++) {
        const int cur = kt & 1;
        if (kt + 1 < nkt) {
            const int k0 = (kt + 1) << 5;
            const int nxt = cur ^ 1;
            const uint32_t aoff = sA0 + (uint32_t)(nxt * A_TILE64 << 2);
            const uint32_t boff = sB0 + (uint32_t)(nxt * B_TILE << 2);
#pragma unroll
            for (int r = 0; r < 2; r++) {
                int grow = row0 + a_row[r];
                const float* src = A + (size_t)grow * K + k0 + a_kq;
                uint32_t dst = aoff + (uint32_t)((a_row[r] * ASTR + a_kq) << 2);
                CP_ASYNC16(dst, src, grow < M ? 16 : 0);
            }
#pragma unroll
            for (int r = 0; r < 4; r++) {
                const float* src = B + (size_t)(k0 + b_k[r]) * N + col0 + b_nq;
                uint32_t dst = boff + (uint32_t)((b_k[r] * BSTR + b_nq) << 2);
                CP_ASYNC16(dst, src, 16);
            }
            CP_COMMIT();
            CP_WAIT1();
        } else {
            CP_WAIT0();
        }
        __syncthreads();

        const uint32_t* Au = (const uint32_t*)(As + cur * A_TILE64);
        const uint32_t* Bu = (const uint32_t*)(Bs + cur * B_TILE);
#pragma unroll
        for (int s = 0; s < 4; s++) {
            uint32_t a[4];
            {
                const uint32_t* ap = Au + (warp_m * 16 + gid) * ASTR + s * 8 + tig;
                a[0] = ap[0];
                a[1] = ap[8 * ASTR];
                a[2] = ap[4];
                a[3] = ap[8 * ASTR + 4];
            }
            uint32_t b[8][2];
#pragma unroll
            for (int nf = 0; nf < 8; nf++) {
                int nb = warp_n * 64 + nf * 8 + gid;
                b[nf][0] = Bu[(s * 8 + tig) * BSTR + nb];
                b[nf][1] = Bu[(s * 8 + tig + 4) * BSTR + nb];
            }
#pragma unroll
            for (int nf = 0; nf < 8; nf++)
                mma_tf32(acc[nf], a, b[nf]);
        }
        __syncthreads();
    }

    {
        int rbase = row0 + warp_m * 16 + gid;
#pragma unroll
        for (int half = 0; half < 2; half++) {
            int r = rbase + half * 8;
            if (r >= M) continue;
#pragma unroll
            for (int nf = 0; nf < 8; nf++) {
                int cidx = col0 + warp_n * 64 + nf * 8 + tig * 2;
                float2 v;
                v.x = acc[nf][half * 2 + 0] * alpha;
                v.y = acc[nf][half * 2 + 1] * alpha;
                if (bias) { v.x += bias[cidx]; v.y += bias[cidx + 1]; }
                *(float2*)(C + (size_t)r * N + cidx) = v;
            }
        }
    }
}

// =================== tf32 TC g-GEMM (batched per head), bf16 output ===================
#define GSTR 68
#define G_SMEM_FLOATS (64 * GSTR + 128 * GSTR)

__global__ void __launch_bounds__(256, 3) g_tc_kernel(
    const float* __restrict__ q2, const float* __restrict__ Wpkv, uint32_t* __restrict__ g32)
{
    extern __shared__ float sm[];
    float* Asm = sm;
    float* Bsm = sm + 64 * GSTR;

    const int t = threadIdx.x;
    const int lane = t & 31;
    const int warp = t >> 5;
    const int gid = lane >> 2;
    const int tig = lane & 3;
    const int warp_m = warp >> 1;
    const int warp_n = warp & 1;
    const int m0 = blockIdx.x * 64;
    const int n0 = blockIdx.y * 128;
    const int h = blockIdx.z;

#pragma unroll
    for (int r = 0; r < 4; r++) {
        int idx = t + (r << 8);
        int mm = idx >> 4, dv = (idx & 15) << 2;
        float4 v = *(const float4*)(q2 + (size_t)(m0 + mm) * CC + h * 64 + dv);
        *(float4*)(Asm + mm * GSTR + dv) = cvt4(v);
    }
#pragma unroll
    for (int r = 0; r < 8; r++) {
        int idx = t + (r << 8);
        int cc = idx >> 4, dv = (idx & 15) << 2;
        float4 v = *(const float4*)(Wpkv + (size_t)(n0 + cc) * (2 * CC) + h * 64 + dv);
        *(float4*)(Bsm + cc * GSTR + dv) = cvt4(v);
    }
    __syncthreads();

    float acc[8][4];
#pragma unroll
    for (int nf = 0; nf < 8; nf++)
#pragma unroll
        for (int c = 0; c < 4; c++) acc[nf][c] = 0.f;

    const uint32_t* Au = (const uint32_t*)Asm;
    const uint32_t* Bu = (const uint32_t*)Bsm;
#pragma unroll
    for (int s = 0; s < 8; s++) {
        uint32_t a[4];
        const uint32_t* ap = Au + (warp_m * 16 + gid) * GSTR + s * 8 + tig;
        a[0] = ap[0];
        a[1] = ap[8 * GSTR];
        a[2] = ap[4];
        a[3] = ap[8 * GSTR + 4];
#pragma unroll
        for (int nf = 0; nf < 8; nf++) {
            int nb = warp_n * 64 + nf * 8 + gid;
            uint32_t b[2];
            b[0] = Bu[nb * GSTR + s * 8 + tig];
            b[1] = Bu[nb * GSTR + s * 8 + tig + 4];
            mma_tf32(acc[nf], a, b);
        }
    }

#pragma unroll
    for (int half = 0; half < 2; half++) {
        int m = m0 + warp_m * 16 + gid + half * 8;
        uint32_t* grow = g32 + ((size_t)m * HH + h) * (CC / 2) + n0 / 2;
#pragma unroll
        for (int nf = 0; nf < 8; nf++) {
            int col = warp_n * 64 + nf * 8 + tig * 2;
            grow[col >> 1] = pack_bf16(acc[nf][half * 2 + 0], acc[nf][half * 2 + 1]);
        }
    }
}

// ---------------- CLS attention: one block per (b,h) ----------------
__global__ void __launch_bounds__(256) cls_kernel(const float* __restrict__ qkv,
                                                  float* __restrict__ pre)
{
    __shared__ float qv[64];
    __shared__ float logit[NTOK];
    __shared__ float red[256];
    const int bh = blockIdx.x;
    const int b = bh / HH, h = bh % HH;
    const int t = threadIdx.x;
    const int lane = t & 31, warp = t >> 5;
    const float* base = qkv + (size_t)b * NTOK * (3 * CC);

    if (t < 64) qv[t] = base[h * 64 + t] * SCALE;
    __syncthreads();

    for (int n = warp; n < NTOK; n += 8) {
        const float* kr = base + (size_t)n * (3 * CC) + CC + h * 64;
        float2 kv2 = *(const float2*)(kr + lane * 2);
        float s = kv2.x * qv[lane * 2] + kv2.y * qv[lane * 2 + 1];
#pragma unroll
        for (int o = 16; o; o >>= 1) s += __shfl_xor_sync(0xffffffffu, s, o);
        if (lane == 0) logit[n] = s;
    }
    __syncthreads();

    float m = -1e30f;
    for (int n = t; n < NTOK; n += 256) m = fmaxf(m, logit[n]);
    red[t] = m; __syncthreads();
    for (int s2 = 128; s2 > 0; s2 >>= 1) {
        if (t < s2) red[t] = fmaxf(red[t], red[t + s2]);
        __syncthreads();
    }
    const float mx = red[0];
    __syncthreads();

    float ssum = 0.f;
    for (int n = t; n < NTOK; n += 256) {
        float e = __expf(logit[n] - mx);
        logit[n] = e;
        ssum += e;
    }
    red[t] = ssum; __syncthreads();
    for (int s2 = 128; s2 > 0; s2 >>= 1) {
        if (t < s2) red[t] += red[t + s2];
        __syncthreads();
    }
    const float inv = 1.f / red[0];
    __syncthreads();

    const int dd = t & 63, grp = t >> 6;
    float acc = 0.f;
    for (int n = grp; n < NTOK; n += 4)
        acc += logit[n] * base[(size_t)n * (3 * CC) + 2 * CC + h * 64 + dd];
    red[t] = acc; __syncthreads();
    if (t < 64) {
        float v = (red[t] + red[t + 64] + red[t + 128] + red[t + 192]) * inv;
        pre[(size_t)b * NTOK * CC + h * 64 + t] = __uint_as_float(f2tf32(v));
    }
}

// ---------------- tf32 tensor-core spatial attention (+ fused x_diag) ----------------
#define QT 32
#define NPAD 208
#define QSTR 68
#define KSTR 216
#define LSTR 212
#define VSTR 72
#define SPA2_POOL 14976
#define SPA2_SMEM_FLOATS (QT*QSTR + QT*LSTR + SPA2_POOL)

__global__ void __launch_bounds__(128, 2) spatial_tc_kernel(const float* __restrict__ qkv,
                                                            float* __restrict__ traj,
                                                            float* __restrict__ xd)
{
    extern __shared__ float sm[];
    uint32_t* qs = (uint32_t*)sm;
    float* ls = sm + QT * QSTR;
    uint32_t* ks = (uint32_t*)(ls + QT * LSTR);
    uint32_t* vs = ks;

    const int t = threadIdx.x;
    const int lane = t & 31, warp = t >> 5;
    const int gid = lane >> 2, tig = lane & 3;
    const int warp_m = warp >> 1;
    const int warp_n = warp & 1;
    const int bh = blockIdx.y;
    const int b = bh / HH, h = bh % HH;
    const int q0 = blockIdx.x * QT;
    const float* base = qkv + (size_t)b * NTOK * (3 * CC);

#pragma unroll
    for (int r = 0; r < 4; r++) {
        int idx = t + r * 128;
        int q = idx >> 4, dv = (idx & 15) << 2;
        float4 v = *(const float4*)(base + (size_t)(1 + q0 + q) * (3 * CC) + h * 64 + dv);
        uint32_t* dst = qs + q * QSTR + dv;
        dst[0] = f2tf32(v.x * SCALE); dst[1] = f2tf32(v.y * SCALE);
        dst[2] = f2tf32(v.z * SCALE); dst[3] = f2tf32(v.w * SCALE);
    }

    for (int f = 0; f < FF; f++) {
        for (int idx = t; idx < PP * 16; idx += 128) {
            int n = idx >> 4, dv = (idx & 15) << 2;
            float4 v = *(const float4*)(base + (size_t)(1 + f * PP + n) * (3 * CC) + CC + h * 64 + dv);
            ks[(dv + 0) * KSTR + n] = f2tf32(v.x);
            ks[(dv + 1) * KSTR + n] = f2tf32(v.y);
            ks[(dv + 2) * KSTR + n] = f2tf32(v.z);
            ks[(dv + 3) * KSTR + n] = f2tf32(v.w);
        }
        for (int i = t; i < 64 * 12; i += 128) {
            int d = i / 12, n = 196 + (i % 12);
            ks[d * KSTR + n] = 0u;
        }
        __syncthreads();

        {
            float acc[13][4];
#pragma unroll
            for (int nf = 0; nf < 13; nf++)
#pragma unroll
                for (int c = 0; c < 4; c++) acc[nf][c] = 0.f;
#pragma unroll
            for (int s = 0; s < 8; s++) {
                uint32_t a[4];
                const uint32_t* ap = qs + (warp_m * 16 + gid) * QSTR + s * 8 + tig;
                a[0] = ap[0];
                a[1] = ap[8 * QSTR];
                a[2] = ap[4];
                a[3] = ap[8 * QSTR + 4];
#pragma unroll
                for (int nf = 0; nf < 13; nf++) {
                    int nb = warp_n * 104 + nf * 8 + gid;
                    uint32_t bfr[2];
                    bfr[0] = ks[(s * 8 + tig) * KSTR + nb];
                    bfr[1] = ks[(s * 8 + tig + 4) * KSTR + nb];
                    mma_tf32(acc[nf], a, bfr);
                }
            }
#pragma unroll
            for (int nf = 0; nf < 13; nf++) {
                int col = warp_n * 104 + nf * 8 + tig * 2;
                int row = warp_m * 16 + gid;
                *(float2*)(ls + row * LSTR + col) = make_float2(acc[nf][0], acc[nf][1]);
                *(float2*)(ls + (row + 8) * LSTR + col) = make_float2(acc[nf][2], acc[nf][3]);
            }
        }
        __syncthreads();

        for (int idx = t; idx < PP * 16; idx += 128) {
            int n = idx >> 4, dv = (idx & 15) << 2;
            float4 v = *(const float4*)(base + (size_t)(1 + f * PP + n) * (3 * CC) + 2 * CC + h * 64 + dv);
            uint32_t* dst = vs + n * VSTR + dv;
            dst[0] = f2tf32(v.x); dst[1] = f2tf32(v.y);
            dst[2] = f2tf32(v.z); dst[3] = f2tf32(v.w);
        }

        for (int i = 0; i < 8; i++) {
            int qq = warp * 8 + i;
            float* row = ls + qq * LSTR;
            float m = -1e30f;
            for (int n = lane; n < PP; n += 32) m = fmaxf(m, row[n]);
#pragma unroll
            for (int o = 16; o; o >>= 1) m = fmaxf(m, __shfl_xor_sync(0xffffffffu, m, o));
            float ssum = 0.f;
            float ev[7];
            int cnt = 0;
            for (int n = lane; n < PP; n += 32) {
                float e = __expf(row[n] - m);
                ev[cnt++] = e;
                ssum += e;
            }
#pragma unroll
            for (int o = 16; o; o >>= 1) ssum += __shfl_xor_sync(0xffffffffu, ssum, o);
            float inv = 1.f / ssum;
            cnt = 0;
            for (int n = lane; n < PP; n += 32)
                ((uint32_t*)row)[n] = f2tf32(ev[cnt++] * inv);
            if (lane < 12) ((uint32_t*)row)[196 + lane] = 0u;
        }
        __syncthreads();

        {
            float acc[4][4];
#pragma unroll
            for (int nf = 0; nf < 4; nf++)
#pragma unroll
                for (int c = 0; c < 4; c++) acc[nf][c] = 0.f;
            const uint32_t* lsu = (const uint32_t*)ls;
#pragma unroll
            for (int s = 0; s < 26; s++) {
                uint32_t a[4];
                const uint32_t* ap = lsu + (warp_m * 16 + gid) * LSTR + s * 8 + tig;
                a[0] = ap[0];
                a[1] = ap[8 * LSTR];
                a[2] = ap[4];
                a[3] = ap[8 * LSTR + 4];
#pragma unroll
                for (int nf = 0; nf < 4; nf++) {
                    int nb = warp_n * 32 + nf * 8 + gid;
                    uint32_t bfr[2];
                    bfr[0] = vs[(s * 8 + tig) * VSTR + nb];
                    bfr[1] = vs[(s * 8 + tig + 4) * VSTR + nb];
                    mma_tf32(acc[nf], a, bfr);
                }
            }
#pragma unroll
            for (int half = 0; half < 2; half++) {
                int q = q0 + warp_m * 16 + gid + half * 8;
                float* orow = traj + (((size_t)(b * SS + q) * FF + f) * CC + h * 64);
                const bool diag = (f == q / PP);
                float* xrow = xd + ((size_t)(b * SS + q) * CC + h * 64);
#pragma unroll
                for (int nf = 0; nf < 4; nf++) {
                    int col = warp_n * 32 + nf * 8 + tig * 2;
                    float2 v = make_float2(acc[nf][half * 2 + 0], acc[nf][half * 2 + 1]);
                    *(float2*)(orow + col) = v;
                    if (diag) {
                        float2 vr;
                        vr.x = __uint_as_float(f2tf32(v.x));
                        vr.y = __uint_as_float(f2tf32(v.y));
                        *(float2*)(xrow + col) = vr;
                    }
                }
            }
        }
        __syncthreads();
    }
}

// ---------------- phase-2: logits + softmax + output + attn write ----------------
#define P2_SMEM_FLOATS (FF * CC + HH * CC + 96 + 96)
__global__ void __launch_bounds__(256) phase2_kernel(
    const float* __restrict__ traj, const uint32_t* __restrict__ g32,
    float* __restrict__ pre, float* __restrict__ attn_out, int write_attn)
{
    extern __shared__ float sm[];
    float* trs = sm;
    float* gs = sm + FF * CC;
    float* lsm = gs + HH * CC;
    float* am = lsm + 96;

    const int bs = blockIdx.x;
    const int b = bs / SS, s = bs % SS;
    const int t = threadIdx.x;

    const float* tr = traj + (size_t)bs * FF * CC;
    for (int i = t; i < FF * CC / 4; i += 256)
        ((float4*)trs)[i] = ((const float4*)tr)[i];
    const uint32_t* gg = g32 + (size_t)bs * HH * (CC / 2);
    for (int i = t; i < HH * CC / 2; i += 256) {
        uint32_t w = gg[i];
        float2 v;
        v.x = __uint_as_float(w << 16);
        v.y = __uint_as_float(w & 0xffff0000u);
        *(float2*)(gs + 2 * i) = v;
    }
    __syncthreads();

    {
        const int lane = t & 31, w = t >> 5;
        for (int p = w * 12; p < w * 12 + 12; p++) {
            int h = p >> 3, f = p & 7;
            float ssum = 0.f;
            for (int c = lane; c < CC; c += 32)
                ssum += trs[f * CC + c] * gs[h * CC + c];
#pragma unroll
            for (int o = 16; o; o >>= 1) ssum += __shfl_xor_sync(0xffffffffu, ssum, o);
            if (lane == 0) lsm[p] = ssum;
        }
    }
    __syncthreads();

    if (t < HH) {
        int h = t;
        float m = -1e30f;
#pragma unroll
        for (int f = 0; f < FF; f++) m = fmaxf(m, lsm[h * 8 + f]);
        float e[FF];
        float ssum = 0.f;
#pragma unroll
        for (int f = 0; f < FF; f++) { e[f] = __expf(lsm[h * 8 + f] - m); ssum += e[f]; }
        float inv = 1.f / ssum;
#pragma unroll
        for (int f = 0; f < FF; f++) am[h * 8 + f] = e[f] * inv;
    }
    __syncthreads();

    if (write_attn && t < 96) {
        int h = t >> 3, f = t & 7;
        attn_out[(((size_t)b * HH + h) * SS + s) * FF + f] = am[t];
    }

    for (int c = t; c < CC; c += 256) {
        int h = c >> 6;
        float acc = 0.f;
#pragma unroll
        for (int f = 0; f < FF; f++) acc += am[h * 8 + f] * trs[f * CC + c];
        pre[((size_t)b * NTOK + 1 + s) * CC + c] = __uint_as_float(f2tf32(acc));
    }
}

// ---------------- host ----------------
extern "C" void kernel_launch(void* const* d_in, const int* in_sizes, int n_in,
                              void* d_out, int out_size)
{
    const float* x     = (const float*)d_in[0];
    const float* Wqkv  = (const float*)d_in[1];
    const float* Wpq   = (const float*)d_in[2];
    const float* Wpkv  = (const float*)d_in[3];
    const float* Wproj = (const float*)d_in[4];
    const float* bproj = (const float*)d_in[5];

    float *qkv, *traj, *xd, *q2, *gb, *pre, *xr, *wr;
    cudaGetSymbolAddress((void**)&qkv,  g_qkv);
    cudaGetSymbolAddress((void**)&traj, g_traj);
    cudaGetSymbolAddress((void**)&xd,   g_xd);
    cudaGetSymbolAddress((void**)&q2,   g_q2v);
    cudaGetSymbolAddress((void**)&gb,   g_gb);
    cudaGetSymbolAddress((void**)&pre,  g_pre);
    cudaGetSymbolAddress((void**)&xr,   g_xr);
    cudaGetSymbolAddress((void**)&wr,   g_wr);
    uint32_t* g32 = (uint32_t*)gb;

    float* wqkv_r  = wr;
    float* wpq_r   = wr + (size_t)CC * 3 * CC;
    float* wproj_r = wpq_r + (size_t)CC * CC;

    const size_t OUT_MAIN = (size_t)BB * NTOK * CC;
    const size_t OUT_ATTN = (size_t)BB * HH * SS * FF;
    int write_attn = ((size_t)out_size >= OUT_MAIN + OUT_ATTN) ? 1 : 0;
    float* attn_ptr = (float*)d_out + OUT_MAIN;

    const int sg_smem   = SG_SMEM_FLOATS * 4;
    const int sg64_smem = SG64_SMEM_FLOATS * 4;
    const int g_smem    = G_SMEM_FLOATS * 4;
    const int spa_smem  = SPA2_SMEM_FLOATS * 4;
    const int p2_smem   = P2_SMEM_FLOATS * 4;
    cudaFuncSetAttribute(sgemm_tf32_kernel,   cudaFuncAttributeMaxDynamicSharedMemorySize, sg_smem);
    cudaFuncSetAttribute(sgemm64_tf32_kernel, cudaFuncAttributeMaxDynamicSharedMemorySize, sg64_smem);
    cudaFuncSetAttribute(g_tc_kernel,         cudaFuncAttributeMaxDynamicSharedMemorySize, g_smem);
    cudaFuncSetAttribute(spatial_tc_kernel,   cudaFuncAttributeMaxDynamicSharedMemorySize, spa_smem);
    cudaFuncSetAttribute(phase2_kernel,       cudaFuncAttributeMaxDynamicSharedMemorySize, p2_smem);

    // 0) pre-round x + weights to tf32 (producers handle the other GEMM inputs)
    {
        int n4;
        n4 = (BB * NTOK * CC) / 4;
        round_tf32_kernel<<<(n4 + 255) / 256, 256>>>(x, xr, n4);
        n4 = (CC * 3 * CC) / 4;
        round_tf32_kernel<<<(n4 + 255) / 256, 256>>>(Wqkv, wqkv_r, n4);
        n4 = (CC * CC) / 4;
        round_tf32_kernel<<<(n4 + 255) / 256, 256>>>(Wpq, wpq_r, n4);
        round_tf32_kernel<<<(n4 + 255) / 256, 256>>>(Wproj, wproj_r, n4);
    }

    // 1) qkv = x @ W_qkv  [pure-TC 128-tile, pre-rounded inputs]
    sgemm_tf32_kernel<<<dim3((3 * CC) / 128, (BB * NTOK + 127) / 128), 256, sg_smem>>>(
        xr, wqkv_r, qkv, BB * NTOK, 3 * CC, CC, 1.0f, nullptr, 0);

    // 2) CLS attention -> pre[b, 0, :] (tf32-rounded store)
    cls_kernel<<<BB * HH, 256>>>(qkv, pre);

    // 3) spatial attention -> traj, fused tf32-rounded x_diag -> xd
    spatial_tc_kernel<<<dim3(SS / QT, BB * HH), 128, spa_smem>>>(qkv, traj, xd);

    // 4) q2 = scale * xd @ W_pq  [pure-TC 64-tile]
    sgemm64_tf32_kernel<<<dim3(CC / 128, (BB * SS + 63) / 64), 256, sg64_smem>>>(
        xd, wpq_r, q2, BB * SS, CC, CC, SCALE, nullptr);

    // 5) g = per-head W_pk @ q2  [TC, bf16 output]
    g_tc_kernel<<<dim3((BB * SS) / 64, CC / 128, HH), 256, g_smem>>>(q2, Wpkv, g32);

    // 6) phase-2 attention (tf32-rounded pre store)
    phase2_kernel<<<BB * SS, 256, p2_smem>>>(traj, g32, pre, attn_ptr, write_attn);

    // 7) out = pre @ W_proj + b_proj  [pure-TC 64-tile]
    sgemm64_tf32_kernel<<<dim3(CC / 128, (BB * NTOK + 63) / 64), 256, sg64_smem>>>(
        pre, wproj_r, (float*)d_out, BB * NTOK, CC, CC, 1.0f, bproj);
}